// round 11
// baseline (speedup 1.0000x reference)
#include <cuda_runtime.h>
#include <math.h>
#include <stdint.h>

// Problem constants
#define BB 2
#define SS 2048
#define HH 2048
#define NH 16
#define HD 128
#define SCALE 0.08838834764831845f  // 1/sqrt(128)

// ---------------- scratch (device globals; no allocation allowed) ----------
__device__ float g_q[(size_t)BB * NH * SS * HD];
__device__ float g_k[(size_t)BB * NH * SS * HD];
__device__ float g_v[(size_t)BB * NH * SS * HD];
__device__ float g_att[(size_t)BB * SS * HH];

// ---------------- shared mma helpers (HW-validated rounds 8-9) -------------
__device__ __forceinline__ uint32_t tf32_hi_bits(float x) {
    return __float_as_uint(x) & 0xFFFFE000u;
}
__device__ __forceinline__ void split_tf32(float f, uint32_t& h, uint32_t& l) {
    h = tf32_hi_bits(f);
    l = tf32_hi_bits(f - __uint_as_float(h));
}
__device__ __forceinline__ void split_store4(uint32_t* H, uint32_t* L, int off,
                                             float4 v) {
    uint4 h, l;
    split_tf32(v.x, h.x, l.x);
    split_tf32(v.y, h.y, l.y);
    split_tf32(v.z, h.z, l.z);
    split_tf32(v.w, h.w, l.w);
    *(uint4*)&H[off] = h;
    *(uint4*)&L[off] = l;
}
__device__ __forceinline__ void mma_tf32(float* c,
                                         const uint32_t* a,
                                         const uint32_t* b) {
    asm volatile(
        "mma.sync.aligned.m16n8k8.row.col.f32.tf32.tf32.f32 "
        "{%0,%1,%2,%3}, {%4,%5,%6,%7}, {%8,%9}, {%0,%1,%2,%3};"
        : "+f"(c[0]), "+f"(c[1]), "+f"(c[2]), "+f"(c[3])
        : "r"(a[0]), "r"(a[1]), "r"(a[2]), "r"(a[3]),
          "r"(b[0]), "r"(b[1]));
}

// ---------------- 3xTF32 GEMM, pre-split smem + term-major mma -------------
// C[m,n] = sum_k A[m,k]*W[n,k] (NT). BM=BN=128, BK=16, 256 thr, 8 warps 2x4.
#define BKT_G 16
#define GP 20                    // u32 pitch; (20g+tg) banks distinct
#define GARR 2560                // u32 per buffer per array (128*20)
#define GEMM_SMEM (8 * GARR * 4) // Ah,Al,Wh,Wl x 2 buffers = 81920 B

template <int MODE>
__device__ __forceinline__ void gemm_tf32_body(const float* __restrict__ A,
                                               const float* __restrict__ W,
                                               float* __restrict__ C,
                                               int K, int N) {
    extern __shared__ uint32_t gsm[];
    uint32_t* AH = gsm;               // [2][128][20]
    uint32_t* AL = gsm + 2 * GARR;
    uint32_t* WH = gsm + 4 * GARR;
    uint32_t* WL = gsm + 6 * GARR;

    const int bn = blockIdx.x;
    const int bm = blockIdx.y;
    const int t  = threadIdx.x;
    const int wid  = t >> 5;
    const int lane = t & 31;
    const int g  = lane >> 2;
    const int tg = lane & 3;

    const int wm = (wid & 1) * 64;
    const int wn = (wid >> 1) * 32;

    const float* Ablk = A + (size_t)(bm * 128) * K;
    const float* Wblk = W + (size_t)(bn * 128) * K;

    const int r0 = t >> 2;           // 0..63
    const int q0 = (t & 3) * 4;
    const int r1 = r0 + 64;          // 64..127

    float acc[4][4][4];
#pragma unroll
    for (int i = 0; i < 4; i++)
#pragma unroll
        for (int j = 0; j < 4; j++)
#pragma unroll
            for (int r = 0; r < 4; r++) acc[i][j][r] = 0.f;

    // prologue: stage K-tile 0 into buffer 0 (pre-split)
    split_store4(AH, AL, r0 * GP + q0, *(const float4*)(Ablk + (size_t)r0 * K + q0));
    split_store4(AH, AL, r1 * GP + q0, *(const float4*)(Ablk + (size_t)r1 * K + q0));
    split_store4(WH, WL, r0 * GP + q0, *(const float4*)(Wblk + (size_t)r0 * K + q0));
    split_store4(WH, WL, r1 * GP + q0, *(const float4*)(Wblk + (size_t)r1 * K + q0));
    __syncthreads();

    int buf = 0;
    for (int kt = 0; kt < K; kt += BKT_G) {
        const bool has_next = (kt + BKT_G) < K;
        float4 pa0, pa1, pw0, pw1;
        if (has_next) {
            pa0 = *(const float4*)(Ablk + (size_t)r0 * K + kt + BKT_G + q0);
            pa1 = *(const float4*)(Ablk + (size_t)r1 * K + kt + BKT_G + q0);
            pw0 = *(const float4*)(Wblk + (size_t)r0 * K + kt + BKT_G + q0);
            pw1 = *(const float4*)(Wblk + (size_t)r1 * K + kt + BKT_G + q0);
        }
        const int bo = buf * GARR;

#pragma unroll
        for (int k0 = 0; k0 < BKT_G; k0 += 8) {
            uint32_t Ah[4][4], Al[4][4];
            uint32_t Bh[4][2], Bl[4][2];
#pragma unroll
            for (int i = 0; i < 4; i++) {
                int row = (wm + i * 16 + g) * GP + bo;
                Ah[i][0] = AH[row + k0 + tg];
                Ah[i][1] = AH[row + 8 * GP + k0 + tg];
                Ah[i][2] = AH[row + k0 + tg + 4];
                Ah[i][3] = AH[row + 8 * GP + k0 + tg + 4];
                Al[i][0] = AL[row + k0 + tg];
                Al[i][1] = AL[row + 8 * GP + k0 + tg];
                Al[i][2] = AL[row + k0 + tg + 4];
                Al[i][3] = AL[row + 8 * GP + k0 + tg + 4];
            }
#pragma unroll
            for (int j = 0; j < 4; j++) {
                int col = (wn + j * 8 + g) * GP + bo;
                Bh[j][0] = WH[col + k0 + tg];
                Bh[j][1] = WH[col + k0 + tg + 4];
                Bl[j][0] = WL[col + k0 + tg];
                Bl[j][1] = WL[col + k0 + tg + 4];
            }
            // term-major: 16 independent accs per pass, no RAW chains
#pragma unroll
            for (int i = 0; i < 4; i++)
#pragma unroll
                for (int j = 0; j < 4; j++) mma_tf32(acc[i][j], Ah[i], Bh[j]);
#pragma unroll
            for (int i = 0; i < 4; i++)
#pragma unroll
                for (int j = 0; j < 4; j++) mma_tf32(acc[i][j], Ah[i], Bl[j]);
#pragma unroll
            for (int i = 0; i < 4; i++)
#pragma unroll
                for (int j = 0; j < 4; j++) mma_tf32(acc[i][j], Al[i], Bh[j]);
        }

        if (has_next) {
            int nb = (buf ^ 1) * GARR;
            split_store4(AH, AL, nb + r0 * GP + q0, pa0);
            split_store4(AH, AL, nb + r1 * GP + q0, pa1);
            split_store4(WH, WL, nb + r0 * GP + q0, pw0);
            split_store4(WH, WL, nb + r1 * GP + q0, pw1);
            __syncthreads();
        }
        buf ^= 1;
    }

#pragma unroll
    for (int i = 0; i < 4; i++) {
#pragma unroll
        for (int j = 0; j < 4; j++) {
            int m0 = bm * 128 + wm + i * 16 + g;
            int n0 = bn * 128 + wn + j * 8 + tg * 2;
#pragma unroll
            for (int r = 0; r < 4; r++) {
                int m = m0 + (r >> 1) * 8;
                int n = n0 + (r & 1);
                if (MODE == 0) {
                    int b  = m >> 11;
                    int s  = m & (SS - 1);
                    int nh = n >> 7;
                    int hd = n & (HD - 1);
                    size_t o = ((((size_t)b * NH + nh) << 11) + s) * HD + hd;
                    C[o] = acc[i][j][r];
                } else {
                    C[(size_t)m * N + n] = acc[i][j][r];
                }
            }
        }
    }
}

__global__ void __launch_bounds__(256) sgemm_qkv(
    const float* __restrict__ A,
    const float* __restrict__ Wq, const float* __restrict__ Wk,
    const float* __restrict__ Wv,
    float* __restrict__ q, float* __restrict__ k, float* __restrict__ v) {
    const float* W = (blockIdx.z == 0) ? Wq : (blockIdx.z == 1) ? Wk : Wv;
    float* C       = (blockIdx.z == 0) ? q  : (blockIdx.z == 1) ? k  : v;
    gemm_tf32_body<0>(A, W, C, HH, HH);
}

__global__ void __launch_bounds__(256) sgemm_out(
    const float* __restrict__ A, const float* __restrict__ W,
    float* __restrict__ C) {
    gemm_tf32_body<1>(A, W, C, HH, HH);
}

// ---------------- RoPE (unchanged) -----------------------------------------
__global__ void __launch_bounds__(256) rope_kernel(
    float* __restrict__ q, float* __restrict__ k,
    const float* __restrict__ cosp, const float* __restrict__ sinp) {
    const int total = BB * NH * SS * (HD / 2);
    int idx = blockIdx.x * blockDim.x + threadIdx.x;
    float* ptr = q;
    if (idx >= total) { idx -= total; ptr = k; }
    if (idx >= total) return;

    int hd = idx & 63;
    int ro = idx >> 6;
    int s  = ro & (SS - 1);
    size_t base = (size_t)ro * HD;

    float x1 = ptr[base + hd];
    float x2 = ptr[base + hd + 64];
    float c1 = cosp[s * HD + hd];
    float s1 = sinp[s * HD + hd];
    float c2 = cosp[s * HD + hd + 64];
    float s2 = sinp[s * HD + hd + 64];
    ptr[base + hd]      = x1 * c1 - x2 * s1;
    ptr[base + hd + 64] = x2 * c2 + x1 * s2;
}

// ---------------- Tensorized flash, pre-split K/Vt + P-shuffle -------------
// CTA: 128 q-rows x 64 k-col tiles, 8 warps, warp owns 16 S/O rows.
// K and Vt pre-split (hi/lo tf32) in smem at staging; Q split on the fly.
// PV A-fragment built from S C-fragment registers via quad shuffles (no Ps).
#define BQF 128
#define BKF 64
#define QP  132
#define VP  68
// smem (u32 words): Qs f32[128*132], KH/KL u32[64*132], VTH/VTL u32[128*68]
#define FS_QS  0
#define FS_KH  (BQF * QP)                 // 16896
#define FS_KL  (FS_KH + BKF * QP)         // 25344
#define FS_VTH (FS_KL + BKF * QP)         // 33792
#define FS_VTL (FS_VTH + HD * VP)         // 42496
#define FLASH2_SMEM ((FS_VTL + HD * VP) * 4)  // 204800 B

__global__ void __launch_bounds__(256, 1) flash_mma_kernel(
    const float* __restrict__ q, const float* __restrict__ k,
    const float* __restrict__ v, float* __restrict__ out) {
    extern __shared__ uint32_t fsm[];
    float*    Qs  = (float*)fsm;
    uint32_t* KH  = fsm + FS_KH;
    uint32_t* KL  = fsm + FS_KL;
    uint32_t* VTH = fsm + FS_VTH;
    uint32_t* VTL = fsm + FS_VTL;

    const int qt = (SS / BQF - 1) - blockIdx.x;   // heavy tiles first
    const int nh = blockIdx.y;
    const int b  = blockIdx.z;
    const int bh = b * NH + nh;
    const float* qb = q + (size_t)bh * SS * HD;
    const float* kb = k + (size_t)bh * SS * HD;
    const float* vb = v + (size_t)bh * SS * HD;

    const int tid  = threadIdx.x;
    const int wid  = tid >> 5;
    const int lane = tid & 31;
    const int g  = lane >> 2;
    const int tg = lane & 3;
    const int r0 = wid * 16 + g;
    const int qg0 = qt * BQF + r0;
    const int qg1 = qg0 + 8;

    // load Q tile (plain floats)
    for (int i = tid; i < BQF * (HD / 4); i += 256) {
        int row = i >> 5, c4 = i & 31;
        *(float4*)&Qs[row * QP + c4 * 4] =
            ((const float4*)(qb + (size_t)(qt * BQF + row) * HD))[c4];
    }

    float o[16][4];
#pragma unroll
    for (int j = 0; j < 16; j++)
#pragma unroll
        for (int r = 0; r < 4; r++) o[j][r] = 0.f;
    float m0 = -INFINITY, m1 = -INFINITY, l0 = 0.f, l1 = 0.f;

    const int nkt = 2 * qt + 2;
    for (int kt = 0; kt < nkt; ++kt) {
        __syncthreads();   // prior tile's mma reads done before overwrite
        for (int i = tid; i < BKF * (HD / 4); i += 256) {
            int row = i >> 5, c4 = i & 31;
            float4 k4 = ((const float4*)(kb + (size_t)(kt * BKF + row) * HD))[c4];
            split_store4(KH, KL, row * QP + c4 * 4, k4);
            float4 v4 = ((const float4*)(vb + (size_t)(kt * BKF + row) * HD))[c4];
            uint32_t h, l;
            split_tf32(v4.x, h, l); VTH[(c4*4+0)*VP + row] = h; VTL[(c4*4+0)*VP + row] = l;
            split_tf32(v4.y, h, l); VTH[(c4*4+1)*VP + row] = h; VTL[(c4*4+1)*VP + row] = l;
            split_tf32(v4.z, h, l); VTH[(c4*4+2)*VP + row] = h; VTL[(c4*4+2)*VP + row] = l;
            split_tf32(v4.w, h, l); VTH[(c4*4+3)*VP + row] = h; VTL[(c4*4+3)*VP + row] = l;
        }
        __syncthreads();

        // ---- S = Q K^T ----
        float s[8][4];
#pragma unroll
        for (int j = 0; j < 8; j++)
#pragma unroll
            for (int r = 0; r < 4; r++) s[j][r] = 0.f;

        for (int k0 = 0; k0 < HD; k0 += 8) {
            uint32_t qh[4], ql[4];
            split_tf32(Qs[r0 * QP + k0 + tg],           qh[0], ql[0]);
            split_tf32(Qs[(r0 + 8) * QP + k0 + tg],     qh[1], ql[1]);
            split_tf32(Qs[r0 * QP + k0 + tg + 4],       qh[2], ql[2]);
            split_tf32(Qs[(r0 + 8) * QP + k0 + tg + 4], qh[3], ql[3]);
            uint32_t bh[8][2], bl[8][2];
#pragma unroll
            for (int nj = 0; nj < 8; nj++) {
                int col = (nj * 8 + g) * QP;
                bh[nj][0] = KH[col + k0 + tg];
                bh[nj][1] = KH[col + k0 + tg + 4];
                bl[nj][0] = KL[col + k0 + tg];
                bl[nj][1] = KL[col + k0 + tg + 4];
            }
#pragma unroll
            for (int nj = 0; nj < 8; nj++) mma_tf32(s[nj], qh, bh[nj]);
#pragma unroll
            for (int nj = 0; nj < 8; nj++) mma_tf32(s[nj], qh, bl[nj]);
#pragma unroll
            for (int nj = 0; nj < 8; nj++) mma_tf32(s[nj], ql, bh[nj]);
        }

        // ---- online softmax; p written back into s registers ----
        const int colbase = kt * BKF + tg * 2;
        float rm0 = -INFINITY, rm1 = -INFINITY;
#pragma unroll
        for (int nj = 0; nj < 8; nj++) {
#pragma unroll
            for (int e = 0; e < 2; e++) {
                int c = colbase + nj * 8 + e;
                float v0 = s[nj][e] * SCALE;
                if (c > qg0) v0 = -INFINITY;
                s[nj][e] = v0;
                rm0 = fmaxf(rm0, v0);
                float v1 = s[nj][2 + e] * SCALE;
                if (c > qg1) v1 = -INFINITY;
                s[nj][2 + e] = v1;
                rm1 = fmaxf(rm1, v1);
            }
        }
        rm0 = fmaxf(rm0, __shfl_xor_sync(0xffffffffu, rm0, 1));
        rm0 = fmaxf(rm0, __shfl_xor_sync(0xffffffffu, rm0, 2));
        rm1 = fmaxf(rm1, __shfl_xor_sync(0xffffffffu, rm1, 1));
        rm1 = fmaxf(rm1, __shfl_xor_sync(0xffffffffu, rm1, 2));

        float mn0 = fmaxf(m0, rm0), mn1 = fmaxf(m1, rm1);
        float cr0 = __expf(m0 - mn0), cr1 = __expf(m1 - mn1);
        float rs0 = 0.f, rs1 = 0.f;
#pragma unroll
        for (int nj = 0; nj < 8; nj++) {
            float p0 = __expf(s[nj][0] - mn0);
            float p1 = __expf(s[nj][1] - mn0);
            float p2 = __expf(s[nj][2] - mn1);
            float p3 = __expf(s[nj][3] - mn1);
            rs0 += p0 + p1;
            rs1 += p2 + p3;
            s[nj][0] = p0; s[nj][1] = p1; s[nj][2] = p2; s[nj][3] = p3;
        }
        rs0 += __shfl_xor_sync(0xffffffffu, rs0, 1);
        rs0 += __shfl_xor_sync(0xffffffffu, rs0, 2);
        rs1 += __shfl_xor_sync(0xffffffffu, rs1, 1);
        rs1 += __shfl_xor_sync(0xffffffffu, rs1, 2);
        l0 = l0 * cr0 + rs0;
        l1 = l1 * cr1 + rs1;
        m0 = mn0; m1 = mn1;
#pragma unroll
        for (int j = 0; j < 16; j++) {
            o[j][0] *= cr0; o[j][1] *= cr0;
            o[j][2] *= cr1; o[j][3] *= cr1;
        }

        // ---- O += P V; P A-fragment via quad shuffles of s C-fragment ----
        for (int k0 = 0; k0 < BKF; k0 += 8) {
            const int njs = k0 >> 3;
            const int srcA = (lane & 0x1C) | (tg >> 1);
            const int srcB = (lane & 0x1C) | ((tg >> 1) + 2);
            float v00 = __shfl_sync(0xffffffffu, s[njs][0], srcA);
            float v01 = __shfl_sync(0xffffffffu, s[njs][1], srcA);
            float v02 = __shfl_sync(0xffffffffu, s[njs][2], srcA);
            float v03 = __shfl_sync(0xffffffffu, s[njs][3], srcA);
            float v10 = __shfl_sync(0xffffffffu, s[njs][0], srcB);
            float v11 = __shfl_sync(0xffffffffu, s[njs][1], srcB);
            float v12 = __shfl_sync(0xffffffffu, s[njs][2], srcB);
            float v13 = __shfl_sync(0xffffffffu, s[njs][3], srcB);
            float a0 = (tg & 1) ? v01 : v00;   // P[r0   ][k0+tg]
            float a1 = (tg & 1) ? v03 : v02;   // P[r0+8 ][k0+tg]
            float a2 = (tg & 1) ? v11 : v10;   // P[r0   ][k0+tg+4]
            float a3 = (tg & 1) ? v13 : v12;   // P[r0+8 ][k0+tg+4]
            uint32_t ph[4], pl[4];
            split_tf32(a0, ph[0], pl[0]);
            split_tf32(a1, ph[1], pl[1]);
            split_tf32(a2, ph[2], pl[2]);
            split_tf32(a3, ph[3], pl[3]);

#pragma unroll
            for (int half = 0; half < 2; half++) {
                uint32_t bh[8][2], bl[8][2];
#pragma unroll
                for (int n2 = 0; n2 < 8; n2++) {
                    int d0 = ((half * 8 + n2) * 8 + g) * VP;
                    bh[n2][0] = VTH[d0 + k0 + tg];
                    bh[n2][1] = VTH[d0 + k0 + tg + 4];
                    bl[n2][0] = VTL[d0 + k0 + tg];
                    bl[n2][1] = VTL[d0 + k0 + tg + 4];
                }
#pragma unroll
                for (int n2 = 0; n2 < 8; n2++) mma_tf32(o[half * 8 + n2], ph, bh[n2]);
#pragma unroll
                for (int n2 = 0; n2 < 8; n2++) mma_tf32(o[half * 8 + n2], ph, bl[n2]);
#pragma unroll
                for (int n2 = 0; n2 < 8; n2++) mma_tf32(o[half * 8 + n2], pl, bh[n2]);
            }
        }
    }

    // ---- normalize + write (B, S, H) ----
    float il0 = 1.0f / l0, il1 = 1.0f / l1;
    float* ob0 = out + ((size_t)(b * SS + qg0)) * HH + nh * HD;
    float* ob1 = out + ((size_t)(b * SS + qg1)) * HH + nh * HD;
#pragma unroll
    for (int nj = 0; nj < 16; nj++) {
        *(float2*)&ob0[nj * 8 + 2 * tg] = make_float2(o[nj][0] * il0, o[nj][1] * il0);
        *(float2*)&ob1[nj * 8 + 2 * tg] = make_float2(o[nj][2] * il1, o[nj][3] * il1);
    }
}

// ---------------- launch ---------------------------------------------------
extern "C" void kernel_launch(void* const* d_in, const int* in_sizes, int n_in,
                              void* d_out, int out_size) {
    const float* hs   = (const float*)d_in[0];
    const float* cosp = (const float*)d_in[1];
    const float* sinp = (const float*)d_in[2];
    const float* Wq   = (const float*)d_in[3];
    const float* Wk   = (const float*)d_in[4];
    const float* Wv   = (const float*)d_in[5];
    const float* Wo   = (const float*)d_in[6];
    float* out = (float*)d_out;

    float *qp, *kp, *vp, *ap;
    cudaGetSymbolAddress((void**)&qp, g_q);
    cudaGetSymbolAddress((void**)&kp, g_k);
    cudaGetSymbolAddress((void**)&vp, g_v);
    cudaGetSymbolAddress((void**)&ap, g_att);

    cudaFuncSetAttribute(sgemm_qkv,
                         cudaFuncAttributeMaxDynamicSharedMemorySize, GEMM_SMEM);
    cudaFuncSetAttribute(sgemm_out,
                         cudaFuncAttributeMaxDynamicSharedMemorySize, GEMM_SMEM);
    cudaFuncSetAttribute(flash_mma_kernel,
                         cudaFuncAttributeMaxDynamicSharedMemorySize, FLASH2_SMEM);

    // 1) QKV projections (fused over grid.z)
    dim3 pg(HH / 128, (BB * SS) / 128, 3);
    sgemm_qkv<<<pg, 256, GEMM_SMEM>>>(hs, Wq, Wk, Wv, qp, kp, vp);

    // 2) RoPE on q and k
    int pairs = 2 * BB * NH * SS * (HD / 2);
    rope_kernel<<<(pairs + 255) / 256, 256>>>(qp, kp, cosp, sinp);

    // 3) causal flash attention (tensor cores)
    dim3 fg(SS / BQF, NH, BB);
    flash_mma_kernel<<<fg, 256, FLASH2_SMEM>>>(qp, kp, vp, ap);

    // 4) output projection
    dim3 og(HH / 128, (BB * SS) / 128, 1);
    sgemm_out<<<og, 256, GEMM_SMEM>>>(ap, Wo, out);
}

// round 12
// speedup vs baseline: 1.2802x; 1.2802x over previous
#include <cuda_runtime.h>
#include <math.h>
#include <stdint.h>

// Problem constants
#define BB 2
#define SS 2048
#define HH 2048
#define NH 16
#define HD 128
#define SCALE 0.08838834764831845f  // 1/sqrt(128)

// ---------------- scratch (device globals; no allocation allowed) ----------
__device__ float g_q[(size_t)BB * NH * SS * HD];
__device__ float g_k[(size_t)BB * NH * SS * HD];
__device__ float g_v[(size_t)BB * NH * SS * HD];
__device__ float g_att[(size_t)BB * SS * HH];

// ---------------- shared mma helpers (HW-validated rounds 8-9) -------------
__device__ __forceinline__ uint32_t tf32_hi_bits(float x) {
    return __float_as_uint(x) & 0xFFFFE000u;
}
__device__ __forceinline__ void split_tf32(float f, uint32_t& h, uint32_t& l) {
    h = tf32_hi_bits(f);
    l = tf32_hi_bits(f - __uint_as_float(h));
}
__device__ __forceinline__ void mma_tf32(float* c,
                                         const uint32_t* a,
                                         const uint32_t* b) {
    asm volatile(
        "mma.sync.aligned.m16n8k8.row.col.f32.tf32.tf32.f32 "
        "{%0,%1,%2,%3}, {%4,%5,%6,%7}, {%8,%9}, {%0,%1,%2,%3};"
        : "+f"(c[0]), "+f"(c[1]), "+f"(c[2]), "+f"(c[3])
        : "r"(a[0]), "r"(a[1]), "r"(a[2]), "r"(a[3]),
          "r"(b[0]), "r"(b[1]));
}

// ---------------- 3xTF32 GEMM (validated R8 layout; +2CTA, term-major) -----
// C[m,n] = sum_k A[m,k]*W[n,k] (NT). BM=BN=128, BK=16, 256 thr, 8 warps 2x4.
#define BKT_G 16
#define SPITCH 20

template <int MODE>
__device__ __forceinline__ void gemm_tf32_body(const float* __restrict__ A,
                                               const float* __restrict__ W,
                                               float* __restrict__ C,
                                               int K, int N) {
    __shared__ float As[2][128][SPITCH];
    __shared__ float Ws[2][128][SPITCH];

    const int bn = blockIdx.x;
    const int bm = blockIdx.y;
    const int t  = threadIdx.x;
    const int wid  = t >> 5;
    const int lane = t & 31;
    const int g  = lane >> 2;
    const int tg = lane & 3;

    const int wm = (wid & 1) * 64;
    const int wn = (wid >> 1) * 32;

    const float* Ablk = A + (size_t)(bm * 128) * K;
    const float* Wblk = W + (size_t)(bn * 128) * K;

    const int r0 = t >> 2;
    const int q0 = (t & 3) * 4;
    const int r1 = (t + 256) >> 2;
    const int q1 = (t & 3) * 4;

    float acc[4][4][4];
#pragma unroll
    for (int i = 0; i < 4; i++)
#pragma unroll
        for (int j = 0; j < 4; j++)
#pragma unroll
            for (int r = 0; r < 4; r++) acc[i][j][r] = 0.f;

    {
        float4 a0 = *(const float4*)(Ablk + (size_t)r0 * K + q0);
        float4 a1 = *(const float4*)(Ablk + (size_t)r1 * K + q1);
        float4 w0 = *(const float4*)(Wblk + (size_t)r0 * K + q0);
        float4 w1 = *(const float4*)(Wblk + (size_t)r1 * K + q1);
        *(float4*)&As[0][r0][q0] = a0;
        *(float4*)&As[0][r1][q1] = a1;
        *(float4*)&Ws[0][r0][q0] = w0;
        *(float4*)&Ws[0][r1][q1] = w1;
    }
    __syncthreads();

    int buf = 0;
    for (int kt = 0; kt < K; kt += BKT_G) {
        const bool has_next = (kt + BKT_G) < K;
        float4 pa0, pa1, pw0, pw1;
        if (has_next) {
            pa0 = *(const float4*)(Ablk + (size_t)r0 * K + kt + BKT_G + q0);
            pa1 = *(const float4*)(Ablk + (size_t)r1 * K + kt + BKT_G + q1);
            pw0 = *(const float4*)(Wblk + (size_t)r0 * K + kt + BKT_G + q0);
            pw1 = *(const float4*)(Wblk + (size_t)r1 * K + kt + BKT_G + q1);
        }

#pragma unroll
        for (int k0 = 0; k0 < BKT_G; k0 += 8) {
            uint32_t Ah[4][4], Al[4][4];
            uint32_t Bh[4][2], Bl[4][2];

#pragma unroll
            for (int i = 0; i < 4; i++) {
                int row = wm + i * 16 + g;
                float f0 = As[buf][row][k0 + tg];
                float f1 = As[buf][row + 8][k0 + tg];
                float f2 = As[buf][row][k0 + tg + 4];
                float f3 = As[buf][row + 8][k0 + tg + 4];
                split_tf32(f0, Ah[i][0], Al[i][0]);
                split_tf32(f1, Ah[i][1], Al[i][1]);
                split_tf32(f2, Ah[i][2], Al[i][2]);
                split_tf32(f3, Ah[i][3], Al[i][3]);
            }
#pragma unroll
            for (int j = 0; j < 4; j++) {
                int col = wn + j * 8 + g;
                float f0 = Ws[buf][col][k0 + tg];
                float f1 = Ws[buf][col][k0 + tg + 4];
                split_tf32(f0, Bh[j][0], Bl[j][0]);
                split_tf32(f1, Bh[j][1], Bl[j][1]);
            }

            // term-major passes: per-acc operand order unchanged (bitwise
            // identical), but no back-to-back RAW on the same accumulator.
#pragma unroll
            for (int i = 0; i < 4; i++)
#pragma unroll
                for (int j = 0; j < 4; j++) mma_tf32(acc[i][j], Ah[i], Bh[j]);
#pragma unroll
            for (int i = 0; i < 4; i++)
#pragma unroll
                for (int j = 0; j < 4; j++) mma_tf32(acc[i][j], Ah[i], Bl[j]);
#pragma unroll
            for (int i = 0; i < 4; i++)
#pragma unroll
                for (int j = 0; j < 4; j++) mma_tf32(acc[i][j], Al[i], Bh[j]);
        }

        if (has_next) {
            int nb = buf ^ 1;
            *(float4*)&As[nb][r0][q0] = pa0;
            *(float4*)&As[nb][r1][q1] = pa1;
            *(float4*)&Ws[nb][r0][q0] = pw0;
            *(float4*)&Ws[nb][r1][q1] = pw1;
            __syncthreads();
        }
        buf ^= 1;
    }

#pragma unroll
    for (int i = 0; i < 4; i++) {
#pragma unroll
        for (int j = 0; j < 4; j++) {
            int m0 = bm * 128 + wm + i * 16 + g;
            int n0 = bn * 128 + wn + j * 8 + tg * 2;
#pragma unroll
            for (int r = 0; r < 4; r++) {
                int m = m0 + (r >> 1) * 8;
                int n = n0 + (r & 1);
                if (MODE == 0) {
                    int b  = m >> 11;
                    int s  = m & (SS - 1);
                    int nh = n >> 7;
                    int hd = n & (HD - 1);
                    size_t o = ((((size_t)b * NH + nh) << 11) + s) * HD + hd;
                    C[o] = acc[i][j][r];
                } else {
                    C[(size_t)m * N + n] = acc[i][j][r];
                }
            }
        }
    }
}

// 2 CTAs/SM: forces regs <= 128 (was 130 -> 1 CTA), doubling warps/SMSP.
__global__ void __launch_bounds__(256, 2) sgemm_qkv(
    const float* __restrict__ A,
    const float* __restrict__ Wq, const float* __restrict__ Wk,
    const float* __restrict__ Wv,
    float* __restrict__ q, float* __restrict__ k, float* __restrict__ v) {
    const float* W = (blockIdx.z == 0) ? Wq : (blockIdx.z == 1) ? Wk : Wv;
    float* C       = (blockIdx.z == 0) ? q  : (blockIdx.z == 1) ? k  : v;
    gemm_tf32_body<0>(A, W, C, HH, HH);
}

__global__ void __launch_bounds__(256, 2) sgemm_out(
    const float* __restrict__ A, const float* __restrict__ W,
    float* __restrict__ C) {
    gemm_tf32_body<1>(A, W, C, HH, HH);
}

// ---------------- RoPE (unchanged) -----------------------------------------
__global__ void __launch_bounds__(256) rope_kernel(
    float* __restrict__ q, float* __restrict__ k,
    const float* __restrict__ cosp, const float* __restrict__ sinp) {
    const int total = BB * NH * SS * (HD / 2);
    int idx = blockIdx.x * blockDim.x + threadIdx.x;
    float* ptr = q;
    if (idx >= total) { idx -= total; ptr = k; }
    if (idx >= total) return;

    int hd = idx & 63;
    int ro = idx >> 6;
    int s  = ro & (SS - 1);
    size_t base = (size_t)ro * HD;

    float x1 = ptr[base + hd];
    float x2 = ptr[base + hd + 64];
    float c1 = cosp[s * HD + hd];
    float s1 = sinp[s * HD + hd];
    float c2 = cosp[s * HD + hd + 64];
    float s2 = sinp[s * HD + hd + 64];
    ptr[base + hd]      = x1 * c1 - x2 * s1;
    ptr[base + hd + 64] = x2 * c2 + x1 * s2;
}

// ---------------- Tensorized flash attention (validated R8 version) --------
#define BQF 128
#define BKF 64
#define QP  132
#define VP  68
#define PP  68
#define SM_QS 0
#define SM_KS (BQF * QP)
#define SM_VT (SM_KS + BKF * QP)
#define SM_PS (SM_VT + HD * VP)
#define FLASH2_SMEM ((SM_PS + BQF * PP) * 4)

__global__ void __launch_bounds__(256, 1) flash_mma_kernel(
    const float* __restrict__ q, const float* __restrict__ k,
    const float* __restrict__ v, float* __restrict__ out) {
    extern __shared__ float sm[];
    float* Qs = sm + SM_QS;   // [128][132]
    float* Ks = sm + SM_KS;   // [64][132]
    float* Vt = sm + SM_VT;   // [128][68]  (row d, col kk)
    float* Ps = sm + SM_PS;   // [128][68]

    const int qt = (SS / BQF - 1) - blockIdx.x;   // heavy tiles first
    const int nh = blockIdx.y;
    const int b  = blockIdx.z;
    const int bh = b * NH + nh;
    const float* qb = q + (size_t)bh * SS * HD;
    const float* kb = k + (size_t)bh * SS * HD;
    const float* vb = v + (size_t)bh * SS * HD;

    const int tid  = threadIdx.x;
    const int wid  = tid >> 5;
    const int lane = tid & 31;
    const int g  = lane >> 2;
    const int tg = lane & 3;
    const int r0 = wid * 16 + g;
    const int qg0 = qt * BQF + r0;
    const int qg1 = qg0 + 8;

    // load Q tile
    for (int i = tid; i < BQF * (HD / 4); i += 256) {
        int row = i >> 5, c4 = i & 31;
        *(float4*)&Qs[row * QP + c4 * 4] =
            ((const float4*)(qb + (size_t)(qt * BQF + row) * HD))[c4];
    }

    float o[16][4];
#pragma unroll
    for (int j = 0; j < 16; j++)
#pragma unroll
        for (int r = 0; r < 4; r++) o[j][r] = 0.f;
    float m0 = -INFINITY, m1 = -INFINITY, l0 = 0.f, l1 = 0.f;

    const int nkt = 2 * qt + 2;
    for (int kt = 0; kt < nkt; ++kt) {
        __syncthreads();
        for (int i = tid; i < BKF * (HD / 4); i += 256) {
            int row = i >> 5, c4 = i & 31;
            *(float4*)&Ks[row * QP + c4 * 4] =
                ((const float4*)(kb + (size_t)(kt * BKF + row) * HD))[c4];
            float4 v4 = ((const float4*)(vb + (size_t)(kt * BKF + row) * HD))[c4];
            Vt[(c4 * 4 + 0) * VP + row] = v4.x;
            Vt[(c4 * 4 + 1) * VP + row] = v4.y;
            Vt[(c4 * 4 + 2) * VP + row] = v4.z;
            Vt[(c4 * 4 + 3) * VP + row] = v4.w;
        }
        __syncthreads();

        // ---- S = Q K^T ----
        float s[8][4];
#pragma unroll
        for (int j = 0; j < 8; j++)
#pragma unroll
            for (int r = 0; r < 4; r++) s[j][r] = 0.f;

        for (int k0 = 0; k0 < HD; k0 += 8) {
            uint32_t Ah[4], Al[4];
            split_tf32(Qs[r0 * QP + k0 + tg],           Ah[0], Al[0]);
            split_tf32(Qs[(r0 + 8) * QP + k0 + tg],     Ah[1], Al[1]);
            split_tf32(Qs[r0 * QP + k0 + tg + 4],       Ah[2], Al[2]);
            split_tf32(Qs[(r0 + 8) * QP + k0 + tg + 4], Ah[3], Al[3]);
#pragma unroll
            for (int nj = 0; nj < 8; nj++) {
                uint32_t Bh[2], Bl[2];
                split_tf32(Ks[(nj * 8 + g) * QP + k0 + tg],     Bh[0], Bl[0]);
                split_tf32(Ks[(nj * 8 + g) * QP + k0 + tg + 4], Bh[1], Bl[1]);
                mma_tf32(s[nj], Ah, Bh);
                mma_tf32(s[nj], Ah, Bl);
                mma_tf32(s[nj], Al, Bh);
            }
        }

        // ---- online softmax ----
        const int colbase = kt * BKF + tg * 2;
        float rm0 = -INFINITY, rm1 = -INFINITY;
#pragma unroll
        for (int nj = 0; nj < 8; nj++) {
#pragma unroll
            for (int e = 0; e < 2; e++) {
                int c = colbase + nj * 8 + e;
                float v0 = s[nj][e] * SCALE;
                if (c > qg0) v0 = -INFINITY;
                s[nj][e] = v0;
                rm0 = fmaxf(rm0, v0);
                float v1 = s[nj][2 + e] * SCALE;
                if (c > qg1) v1 = -INFINITY;
                s[nj][2 + e] = v1;
                rm1 = fmaxf(rm1, v1);
            }
        }
        rm0 = fmaxf(rm0, __shfl_xor_sync(0xffffffffu, rm0, 1));
        rm0 = fmaxf(rm0, __shfl_xor_sync(0xffffffffu, rm0, 2));
        rm1 = fmaxf(rm1, __shfl_xor_sync(0xffffffffu, rm1, 1));
        rm1 = fmaxf(rm1, __shfl_xor_sync(0xffffffffu, rm1, 2));

        float mn0 = fmaxf(m0, rm0), mn1 = fmaxf(m1, rm1);
        float cr0 = __expf(m0 - mn0), cr1 = __expf(m1 - mn1);
        float rs0 = 0.f, rs1 = 0.f;
#pragma unroll
        for (int nj = 0; nj < 8; nj++) {
            float p0 = __expf(s[nj][0] - mn0);
            float p1 = __expf(s[nj][1] - mn0);
            float p2 = __expf(s[nj][2] - mn1);
            float p3 = __expf(s[nj][3] - mn1);
            rs0 += p0 + p1;
            rs1 += p2 + p3;
            *(float2*)&Ps[r0 * PP + nj * 8 + 2 * tg]       = make_float2(p0, p1);
            *(float2*)&Ps[(r0 + 8) * PP + nj * 8 + 2 * tg] = make_float2(p2, p3);
        }
        rs0 += __shfl_xor_sync(0xffffffffu, rs0, 1);
        rs0 += __shfl_xor_sync(0xffffffffu, rs0, 2);
        rs1 += __shfl_xor_sync(0xffffffffu, rs1, 1);
        rs1 += __shfl_xor_sync(0xffffffffu, rs1, 2);
        l0 = l0 * cr0 + rs0;
        l1 = l1 * cr1 + rs1;
        m0 = mn0; m1 = mn1;
#pragma unroll
        for (int j = 0; j < 16; j++) {
            o[j][0] *= cr0; o[j][1] *= cr0;
            o[j][2] *= cr1; o[j][3] *= cr1;
        }
        __syncwarp();   // Ps rows warp-private; publish cross-lane writes

        // ---- O += P V ----
        for (int k0 = 0; k0 < BKF; k0 += 8) {
            uint32_t Ah[4], Al[4];
            split_tf32(Ps[r0 * PP + k0 + tg],           Ah[0], Al[0]);
            split_tf32(Ps[(r0 + 8) * PP + k0 + tg],     Ah[1], Al[1]);
            split_tf32(Ps[r0 * PP + k0 + tg + 4],       Ah[2], Al[2]);
            split_tf32(Ps[(r0 + 8) * PP + k0 + tg + 4], Ah[3], Al[3]);
#pragma unroll
            for (int nj = 0; nj < 16; nj++) {
                uint32_t Bh[2], Bl[2];
                split_tf32(Vt[(nj * 8 + g) * VP + k0 + tg],     Bh[0], Bl[0]);
                split_tf32(Vt[(nj * 8 + g) * VP + k0 + tg + 4], Bh[1], Bl[1]);
                mma_tf32(o[nj], Ah, Bh);
                mma_tf32(o[nj], Ah, Bl);
                mma_tf32(o[nj], Al, Bh);
            }
        }
    }

    // ---- normalize + write (B, S, H) ----
    float il0 = 1.0f / l0, il1 = 1.0f / l1;
    float* ob0 = out + ((size_t)(b * SS + qg0)) * HH + nh * HD;
    float* ob1 = out + ((size_t)(b * SS + qg1)) * HH + nh * HD;
#pragma unroll
    for (int nj = 0; nj < 16; nj++) {
        *(float2*)&ob0[nj * 8 + 2 * tg] = make_float2(o[nj][0] * il0, o[nj][1] * il0);
        *(float2*)&ob1[nj * 8 + 2 * tg] = make_float2(o[nj][2] * il1, o[nj][3] * il1);
    }
}

// ---------------- launch ---------------------------------------------------
extern "C" void kernel_launch(void* const* d_in, const int* in_sizes, int n_in,
                              void* d_out, int out_size) {
    const float* hs   = (const float*)d_in[0];
    const float* cosp = (const float*)d_in[1];
    const float* sinp = (const float*)d_in[2];
    const float* Wq   = (const float*)d_in[3];
    const float* Wk   = (const float*)d_in[4];
    const float* Wv   = (const float*)d_in[5];
    const float* Wo   = (const float*)d_in[6];
    float* out = (float*)d_out;

    float *qp, *kp, *vp, *ap;
    cudaGetSymbolAddress((void**)&qp, g_q);
    cudaGetSymbolAddress((void**)&kp, g_k);
    cudaGetSymbolAddress((void**)&vp, g_v);
    cudaGetSymbolAddress((void**)&ap, g_att);

    cudaFuncSetAttribute(flash_mma_kernel,
                         cudaFuncAttributeMaxDynamicSharedMemorySize,
                         FLASH2_SMEM);

    // 1) QKV projections (fused over grid.z)
    dim3 pg(HH / 128, (BB * SS) / 128, 3);
    sgemm_qkv<<<pg, 256>>>(hs, Wq, Wk, Wv, qp, kp, vp);

    // 2) RoPE on q and k
    int pairs = 2 * BB * NH * SS * (HD / 2);
    rope_kernel<<<(pairs + 255) / 256, 256>>>(qp, kp, cosp, sinp);

    // 3) causal flash attention (tensor cores)
    dim3 fg(SS / BQF, NH, BB);
    flash_mma_kernel<<<fg, 256, FLASH2_SMEM>>>(qp, kp, vp, ap);

    // 4) output projection
    dim3 og(HH / 128, (BB * SS) / 128, 1);
    sgemm_out<<<og, 256>>>(ap, Wo, out);
}

// round 15
// speedup vs baseline: 1.6213x; 1.2664x over previous
#include <cuda_runtime.h>
#include <math.h>
#include <stdint.h>

// Problem constants
#define BB 2
#define SS 2048
#define HH 2048
#define NH 16
#define HD 128
#define SCALE 0.08838834764831845f  // 1/sqrt(128)

// ---------------- scratch (device globals; no allocation allowed) ----------
__device__ float g_q[(size_t)BB * NH * SS * HD];
__device__ float g_k[(size_t)BB * NH * SS * HD];
__device__ float g_v[(size_t)BB * NH * SS * HD];
__device__ float g_att[(size_t)BB * SS * HH];

// ---------------- bf16 split-mma helpers -----------------------------------
// Pack (f0,f1) -> bf16x2 hi (f0 in low half = even-k element) and bf16x2 lo
// (residual). 3-term split: a*b ~= AhBh + AhBl + AlBh (drop AlBl ~2^-16).
__device__ __forceinline__ void split_bf16x2(float f0, float f1,
                                             uint32_t& h, uint32_t& l) {
    uint32_t hp;
    asm("cvt.rn.bf16x2.f32 %0, %1, %2;" : "=r"(hp) : "f"(f1), "f"(f0));
    float h0 = __uint_as_float(hp << 16);
    float h1 = __uint_as_float(hp & 0xFFFF0000u);
    asm("cvt.rn.bf16x2.f32 %0, %1, %2;" : "=r"(l) : "f"(f1 - h1), "f"(f0 - h0));
    h = hp;
}

__device__ __forceinline__ void mma_bf16(float* c,
                                         const uint32_t* a,
                                         const uint32_t* b) {
    asm volatile(
        "mma.sync.aligned.m16n8k16.row.col.f32.bf16.bf16.f32 "
        "{%0,%1,%2,%3}, {%4,%5,%6,%7}, {%8,%9}, {%0,%1,%2,%3};"
        : "+f"(c[0]), "+f"(c[1]), "+f"(c[2]), "+f"(c[3])
        : "r"(a[0]), "r"(a[1]), "r"(a[2]), "r"(a[3]),
          "r"(b[0]), "r"(b[1]));
}

// ---------------- bf16-split GEMM (layout = validated R12 kernel) ----------
// C[m,n] = sum_k A[m,k]*W[n,k] (NT). BM=BN=128, BK=16, 256 thr, 8 warps 2x4.
// One m16n8k16 chunk per K-buffer (K=16). C-fragment layout unchanged.
#define BKT_G 16
#define SPITCH 20

template <int MODE>
__device__ __forceinline__ void gemm_bf16_body(const float* __restrict__ A,
                                               const float* __restrict__ W,
                                               float* __restrict__ C,
                                               int K, int N) {
    __shared__ float As[2][128][SPITCH];
    __shared__ float Ws[2][128][SPITCH];

    const int bn = blockIdx.x;
    const int bm = blockIdx.y;
    const int t  = threadIdx.x;
    const int wid  = t >> 5;
    const int lane = t & 31;
    const int g  = lane >> 2;
    const int tg = lane & 3;

    const int wm = (wid & 1) * 64;
    const int wn = (wid >> 1) * 32;

    const float* Ablk = A + (size_t)(bm * 128) * K;
    const float* Wblk = W + (size_t)(bn * 128) * K;

    const int r0 = t >> 2;
    const int q0 = (t & 3) * 4;
    const int r1 = (t + 256) >> 2;
    const int q1 = (t & 3) * 4;

    float acc[4][4][4];
#pragma unroll
    for (int i = 0; i < 4; i++)
#pragma unroll
        for (int j = 0; j < 4; j++)
#pragma unroll
            for (int r = 0; r < 4; r++) acc[i][j][r] = 0.f;

    {
        float4 a0 = *(const float4*)(Ablk + (size_t)r0 * K + q0);
        float4 a1 = *(const float4*)(Ablk + (size_t)r1 * K + q1);
        float4 w0 = *(const float4*)(Wblk + (size_t)r0 * K + q0);
        float4 w1 = *(const float4*)(Wblk + (size_t)r1 * K + q1);
        *(float4*)&As[0][r0][q0] = a0;
        *(float4*)&As[0][r1][q1] = a1;
        *(float4*)&Ws[0][r0][q0] = w0;
        *(float4*)&Ws[0][r1][q1] = w1;
    }
    __syncthreads();

    int buf = 0;
    for (int kt = 0; kt < K; kt += BKT_G) {
        const bool has_next = (kt + BKT_G) < K;
        float4 pa0, pa1, pw0, pw1;
        if (has_next) {
            pa0 = *(const float4*)(Ablk + (size_t)r0 * K + kt + BKT_G + q0);
            pa1 = *(const float4*)(Ablk + (size_t)r1 * K + kt + BKT_G + q1);
            pw0 = *(const float4*)(Wblk + (size_t)r0 * K + kt + BKT_G + q0);
            pw1 = *(const float4*)(Wblk + (size_t)r1 * K + kt + BKT_G + q1);
        }

        // single m16n8k16 K-chunk per buffer
        {
            uint32_t Ah[4][4], Al[4][4];
            uint32_t Bh[4][2], Bl[4][2];

#pragma unroll
            for (int i = 0; i < 4; i++) {
                int row = wm + i * 16 + g;
                float2 fa;
                fa = *(const float2*)&As[buf][row][2 * tg];
                split_bf16x2(fa.x, fa.y, Ah[i][0], Al[i][0]);
                fa = *(const float2*)&As[buf][row + 8][2 * tg];
                split_bf16x2(fa.x, fa.y, Ah[i][1], Al[i][1]);
                fa = *(const float2*)&As[buf][row][2 * tg + 8];
                split_bf16x2(fa.x, fa.y, Ah[i][2], Al[i][2]);
                fa = *(const float2*)&As[buf][row + 8][2 * tg + 8];
                split_bf16x2(fa.x, fa.y, Ah[i][3], Al[i][3]);
            }
#pragma unroll
            for (int j = 0; j < 4; j++) {
                int col = wn + j * 8 + g;
                float2 fb;
                fb = *(const float2*)&Ws[buf][col][2 * tg];
                split_bf16x2(fb.x, fb.y, Bh[j][0], Bl[j][0]);
                fb = *(const float2*)&Ws[buf][col][2 * tg + 8];
                split_bf16x2(fb.x, fb.y, Bh[j][1], Bl[j][1]);
            }

            // term-major passes: no back-to-back RAW on one accumulator
#pragma unroll
            for (int i = 0; i < 4; i++)
#pragma unroll
                for (int j = 0; j < 4; j++) mma_bf16(acc[i][j], Ah[i], Bh[j]);
#pragma unroll
            for (int i = 0; i < 4; i++)
#pragma unroll
                for (int j = 0; j < 4; j++) mma_bf16(acc[i][j], Ah[i], Bl[j]);
#pragma unroll
            for (int i = 0; i < 4; i++)
#pragma unroll
                for (int j = 0; j < 4; j++) mma_bf16(acc[i][j], Al[i], Bh[j]);
        }

        if (has_next) {
            int nb = buf ^ 1;
            *(float4*)&As[nb][r0][q0] = pa0;
            *(float4*)&As[nb][r1][q1] = pa1;
            *(float4*)&Ws[nb][r0][q0] = pw0;
            *(float4*)&Ws[nb][r1][q1] = pw1;
            __syncthreads();
        }
        buf ^= 1;
    }

#pragma unroll
    for (int i = 0; i < 4; i++) {
#pragma unroll
        for (int j = 0; j < 4; j++) {
            int m0 = bm * 128 + wm + i * 16 + g;
            int n0 = bn * 128 + wn + j * 8 + tg * 2;
#pragma unroll
            for (int r = 0; r < 4; r++) {
                int m = m0 + (r >> 1) * 8;
                int n = n0 + (r & 1);
                if (MODE == 0) {
                    int b  = m >> 11;
                    int s  = m & (SS - 1);
                    int nh = n >> 7;
                    int hd = n & (HD - 1);
                    size_t o = ((((size_t)b * NH + nh) << 11) + s) * HD + hd;
                    C[o] = acc[i][j][r];
                } else {
                    C[(size_t)m * N + n] = acc[i][j][r];
                }
            }
        }
    }
}

__global__ void __launch_bounds__(256, 2) sgemm_qkv(
    const float* __restrict__ A,
    const float* __restrict__ Wq, const float* __restrict__ Wk,
    const float* __restrict__ Wv,
    float* __restrict__ q, float* __restrict__ k, float* __restrict__ v) {
    const float* W = (blockIdx.z == 0) ? Wq : (blockIdx.z == 1) ? Wk : Wv;
    float* C       = (blockIdx.z == 0) ? q  : (blockIdx.z == 1) ? k  : v;
    gemm_bf16_body<0>(A, W, C, HH, HH);
}

__global__ void __launch_bounds__(256, 2) sgemm_out(
    const float* __restrict__ A, const float* __restrict__ W,
    float* __restrict__ C) {
    gemm_bf16_body<1>(A, W, C, HH, HH);
}

// ---------------- RoPE (unchanged, validated) -------------------------------
__global__ void __launch_bounds__(256) rope_kernel(
    float* __restrict__ q, float* __restrict__ k,
    const float* __restrict__ cosp, const float* __restrict__ sinp) {
    const int total = BB * NH * SS * (HD / 2);
    int idx = blockIdx.x * blockDim.x + threadIdx.x;
    float* ptr = q;
    if (idx >= total) { idx -= total; ptr = k; }
    if (idx >= total) return;

    int hd = idx & 63;
    int ro = idx >> 6;
    int s  = ro & (SS - 1);
    size_t base = (size_t)ro * HD;

    float x1 = ptr[base + hd];
    float x2 = ptr[base + hd + 64];
    float c1 = cosp[s * HD + hd];
    float s1 = sinp[s * HD + hd];
    float c2 = cosp[s * HD + hd + 64];
    float s2 = sinp[s * HD + hd + 64];
    ptr[base + hd]      = x1 * c1 - x2 * s1;
    ptr[base + hd + 64] = x2 * c2 + x1 * s2;
}

// ---------------- Tensorized flash attention (bf16 k16 split) --------------
// Structure identical to validated R12 flash; only the inner products use
// m16n8k16 bf16 (half the mma + LDS instruction count).
#define BQF 128
#define BKF 64
#define QP  132
#define VP  68
#define PP  68
#define SM_QS 0
#define SM_KS (BQF * QP)
#define SM_VT (SM_KS + BKF * QP)
#define SM_PS (SM_VT + HD * VP)
#define FLASH2_SMEM ((SM_PS + BQF * PP) * 4)

__global__ void __launch_bounds__(256, 1) flash_mma_kernel(
    const float* __restrict__ q, const float* __restrict__ k,
    const float* __restrict__ v, float* __restrict__ out) {
    extern __shared__ float sm[];
    float* Qs = sm + SM_QS;   // [128][132]
    float* Ks = sm + SM_KS;   // [64][132]
    float* Vt = sm + SM_VT;   // [128][68]
    float* Ps = sm + SM_PS;   // [128][68]

    const int qt = (SS / BQF - 1) - blockIdx.x;   // heavy tiles first
    const int nh = blockIdx.y;
    const int b  = blockIdx.z;
    const int bh = b * NH + nh;
    const float* qb = q + (size_t)bh * SS * HD;
    const float* kb = k + (size_t)bh * SS * HD;
    const float* vb = v + (size_t)bh * SS * HD;

    const int tid  = threadIdx.x;
    const int wid  = tid >> 5;
    const int lane = tid & 31;
    const int g  = lane >> 2;
    const int tg = lane & 3;
    const int r0 = wid * 16 + g;
    const int qg0 = qt * BQF + r0;
    const int qg1 = qg0 + 8;

    for (int i = tid; i < BQF * (HD / 4); i += 256) {
        int row = i >> 5, c4 = i & 31;
        *(float4*)&Qs[row * QP + c4 * 4] =
            ((const float4*)(qb + (size_t)(qt * BQF + row) * HD))[c4];
    }

    float o[16][4];
#pragma unroll
    for (int j = 0; j < 16; j++)
#pragma unroll
        for (int r = 0; r < 4; r++) o[j][r] = 0.f;
    float m0 = -INFINITY, m1 = -INFINITY, l0 = 0.f, l1 = 0.f;

    const int nkt = 2 * qt + 2;
    for (int kt = 0; kt < nkt; ++kt) {
        __syncthreads();
        for (int i = tid; i < BKF * (HD / 4); i += 256) {
            int row = i >> 5, c4 = i & 31;
            *(float4*)&Ks[row * QP + c4 * 4] =
                ((const float4*)(kb + (size_t)(kt * BKF + row) * HD))[c4];
            float4 v4 = ((const float4*)(vb + (size_t)(kt * BKF + row) * HD))[c4];
            Vt[(c4 * 4 + 0) * VP + row] = v4.x;
            Vt[(c4 * 4 + 1) * VP + row] = v4.y;
            Vt[(c4 * 4 + 2) * VP + row] = v4.z;
            Vt[(c4 * 4 + 3) * VP + row] = v4.w;
        }
        __syncthreads();

        // ---- S = Q K^T (m16n8k16 chunks) ----
        float s[8][4];
#pragma unroll
        for (int j = 0; j < 8; j++)
#pragma unroll
            for (int r = 0; r < 4; r++) s[j][r] = 0.f;

        for (int k0 = 0; k0 < HD; k0 += 16) {
            uint32_t Ah[4], Al[4];
            float2 fa;
            fa = *(const float2*)&Qs[r0 * QP + k0 + 2 * tg];
            split_bf16x2(fa.x, fa.y, Ah[0], Al[0]);
            fa = *(const float2*)&Qs[(r0 + 8) * QP + k0 + 2 * tg];
            split_bf16x2(fa.x, fa.y, Ah[1], Al[1]);
            fa = *(const float2*)&Qs[r0 * QP + k0 + 2 * tg + 8];
            split_bf16x2(fa.x, fa.y, Ah[2], Al[2]);
            fa = *(const float2*)&Qs[(r0 + 8) * QP + k0 + 2 * tg + 8];
            split_bf16x2(fa.x, fa.y, Ah[3], Al[3]);
#pragma unroll
            for (int nj = 0; nj < 8; nj++) {
                uint32_t Bh[2], Bl[2];
                float2 fb;
                fb = *(const float2*)&Ks[(nj * 8 + g) * QP + k0 + 2 * tg];
                split_bf16x2(fb.x, fb.y, Bh[0], Bl[0]);
                fb = *(const float2*)&Ks[(nj * 8 + g) * QP + k0 + 2 * tg + 8];
                split_bf16x2(fb.x, fb.y, Bh[1], Bl[1]);
                mma_bf16(s[nj], Ah, Bh);
                mma_bf16(s[nj], Ah, Bl);
                mma_bf16(s[nj], Al, Bh);
            }
        }

        // ---- online softmax (unchanged) ----
        const int colbase = kt * BKF + tg * 2;
        float rm0 = -INFINITY, rm1 = -INFINITY;
#pragma unroll
        for (int nj = 0; nj < 8; nj++) {
#pragma unroll
            for (int e = 0; e < 2; e++) {
                int c = colbase + nj * 8 + e;
                float v0 = s[nj][e] * SCALE;
                if (c > qg0) v0 = -INFINITY;
                s[nj][e] = v0;
                rm0 = fmaxf(rm0, v0);
                float v1 = s[nj][2 + e] * SCALE;
                if (c > qg1) v1 = -INFINITY;
                s[nj][2 + e] = v1;
                rm1 = fmaxf(rm1, v1);
            }
        }
        rm0 = fmaxf(rm0, __shfl_xor_sync(0xffffffffu, rm0, 1));
        rm0 = fmaxf(rm0, __shfl_xor_sync(0xffffffffu, rm0, 2));
        rm1 = fmaxf(rm1, __shfl_xor_sync(0xffffffffu, rm1, 1));
        rm1 = fmaxf(rm1, __shfl_xor_sync(0xffffffffu, rm1, 2));

        float mn0 = fmaxf(m0, rm0), mn1 = fmaxf(m1, rm1);
        float cr0 = __expf(m0 - mn0), cr1 = __expf(m1 - mn1);
        float rs0 = 0.f, rs1 = 0.f;
#pragma unroll
        for (int nj = 0; nj < 8; nj++) {
            float p0 = __expf(s[nj][0] - mn0);
            float p1 = __expf(s[nj][1] - mn0);
            float p2 = __expf(s[nj][2] - mn1);
            float p3 = __expf(s[nj][3] - mn1);
            rs0 += p0 + p1;
            rs1 += p2 + p3;
            *(float2*)&Ps[r0 * PP + nj * 8 + 2 * tg]       = make_float2(p0, p1);
            *(float2*)&Ps[(r0 + 8) * PP + nj * 8 + 2 * tg] = make_float2(p2, p3);
        }
        rs0 += __shfl_xor_sync(0xffffffffu, rs0, 1);
        rs0 += __shfl_xor_sync(0xffffffffu, rs0, 2);
        rs1 += __shfl_xor_sync(0xffffffffu, rs1, 1);
        rs1 += __shfl_xor_sync(0xffffffffu, rs1, 2);
        l0 = l0 * cr0 + rs0;
        l1 = l1 * cr1 + rs1;
        m0 = mn0; m1 = mn1;
#pragma unroll
        for (int j = 0; j < 16; j++) {
            o[j][0] *= cr0; o[j][1] *= cr0;
            o[j][2] *= cr1; o[j][3] *= cr1;
        }
        __syncwarp();   // Ps rows warp-private; publish cross-lane writes

        // ---- O += P V (m16n8k16 chunks) ----
        for (int k0 = 0; k0 < BKF; k0 += 16) {
            uint32_t Ah[4], Al[4];
            float2 fa;
            fa = *(const float2*)&Ps[r0 * PP + k0 + 2 * tg];
            split_bf16x2(fa.x, fa.y, Ah[0], Al[0]);
            fa = *(const float2*)&Ps[(r0 + 8) * PP + k0 + 2 * tg];
            split_bf16x2(fa.x, fa.y, Ah[1], Al[1]);
            fa = *(const float2*)&Ps[r0 * PP + k0 + 2 * tg + 8];
            split_bf16x2(fa.x, fa.y, Ah[2], Al[2]);
            fa = *(const float2*)&Ps[(r0 + 8) * PP + k0 + 2 * tg + 8];
            split_bf16x2(fa.x, fa.y, Ah[3], Al[3]);
#pragma unroll
            for (int nj = 0; nj < 16; nj++) {
                uint32_t Bh[2], Bl[2];
                float2 fb;
                fb = *(const float2*)&Vt[(nj * 8 + g) * VP + k0 + 2 * tg];
                split_bf16x2(fb.x, fb.y, Bh[0], Bl[0]);
                fb = *(const float2*)&Vt[(nj * 8 + g) * VP + k0 + 2 * tg + 8];
                split_bf16x2(fb.x, fb.y, Bh[1], Bl[1]);
                mma_bf16(o[nj], Ah, Bh);
                mma_bf16(o[nj], Ah, Bl);
                mma_bf16(o[nj], Al, Bh);
            }
        }
    }

    float il0 = 1.0f / l0, il1 = 1.0f / l1;
    float* ob0 = out + ((size_t)(b * SS + qg0)) * HH + nh * HD;
    float* ob1 = out + ((size_t)(b * SS + qg1)) * HH + nh * HD;
#pragma unroll
    for (int nj = 0; nj < 16; nj++) {
        *(float2*)&ob0[nj * 8 + 2 * tg] = make_float2(o[nj][0] * il0, o[nj][1] * il0);
        *(float2*)&ob1[nj * 8 + 2 * tg] = make_float2(o[nj][2] * il1, o[nj][3] * il1);
    }
}

// ---------------- launch ---------------------------------------------------
extern "C" void kernel_launch(void* const* d_in, const int* in_sizes, int n_in,
                              void* d_out, int out_size) {
    const float* hs   = (const float*)d_in[0];
    const float* cosp = (const float*)d_in[1];
    const float* sinp = (const float*)d_in[2];
    const float* Wq   = (const float*)d_in[3];
    const float* Wk   = (const float*)d_in[4];
    const float* Wv   = (const float*)d_in[5];
    const float* Wo   = (const float*)d_in[6];
    float* out = (float*)d_out;

    float *qp, *kp, *vp, *ap;
    cudaGetSymbolAddress((void**)&qp, g_q);
    cudaGetSymbolAddress((void**)&kp, g_k);
    cudaGetSymbolAddress((void**)&vp, g_v);
    cudaGetSymbolAddress((void**)&ap, g_att);

    cudaFuncSetAttribute(flash_mma_kernel,
                         cudaFuncAttributeMaxDynamicSharedMemorySize,
                         FLASH2_SMEM);

    // 1) QKV projections (fused over grid.z)
    dim3 pg(HH / 128, (BB * SS) / 128, 3);
    sgemm_qkv<<<pg, 256>>>(hs, Wq, Wk, Wv, qp, kp, vp);

    // 2) RoPE on q and k
    int pairs = 2 * BB * NH * SS * (HD / 2);
    rope_kernel<<<(pairs + 255) / 256, 256>>>(qp, kp, cosp, sinp);

    // 3) causal flash attention (bf16 k16 tensor cores)
    dim3 fg(SS / BQF, NH, BB);
    flash_mma_kernel<<<fg, 256, FLASH2_SMEM>>>(qp, kp, vp, ap);

    // 4) output projection
    dim3 og(HH / 128, (BB * SS) / 128, 1);
    sgemm_out<<<og, 256, 0>>>(ap, Wo, out);
}